// round 1
// baseline (speedup 1.0000x reference)
#include <cuda_runtime.h>
#include <math.h>

#define DT 0.05f
#define NSTEPS 4
#define PTS_PER_BLK 16
#define NTHREADS 256

// Store this thread's 16-float row into the point's 16x16 shared tile,
// with warp-level fencing on both sides (WAR before, RAW after).
__device__ __forceinline__ void put_row(float* Bs, int r, const float v[16]) {
    __syncwarp();
    float4* d = (float4*)(Bs + r * 16);
    d[0] = make_float4(v[0], v[1], v[2], v[3]);
    d[1] = make_float4(v[4], v[5], v[6], v[7]);
    d[2] = make_float4(v[8], v[9], v[10], v[11]);
    d[3] = make_float4(v[12], v[13], v[14], v[15]);
    __syncwarp();
}

// c += a_row * B   (B is the 16x16 tile in shared; a is this thread's row of A)
__device__ __forceinline__ void mm16(float c[16], const float a[16],
                                     const float* Bs) {
#pragma unroll
    for (int k = 0; k < 16; k++) {
        float ak = a[k];
        float4 b0 = *(const float4*)(Bs + k * 16 + 0);
        float4 b1 = *(const float4*)(Bs + k * 16 + 4);
        float4 b2 = *(const float4*)(Bs + k * 16 + 8);
        float4 b3 = *(const float4*)(Bs + k * 16 + 12);
        c[0]  = fmaf(ak, b0.x, c[0]);
        c[1]  = fmaf(ak, b0.y, c[1]);
        c[2]  = fmaf(ak, b0.z, c[2]);
        c[3]  = fmaf(ak, b0.w, c[3]);
        c[4]  = fmaf(ak, b1.x, c[4]);
        c[5]  = fmaf(ak, b1.y, c[5]);
        c[6]  = fmaf(ak, b1.z, c[6]);
        c[7]  = fmaf(ak, b1.w, c[7]);
        c[8]  = fmaf(ak, b2.x, c[8]);
        c[9]  = fmaf(ak, b2.y, c[9]);
        c[10] = fmaf(ak, b2.z, c[10]);
        c[11] = fmaf(ak, b2.w, c[11]);
        c[12] = fmaf(ak, b3.x, c[12]);
        c[13] = fmaf(ak, b3.y, c[13]);
        c[14] = fmaf(ak, b3.z, c[14]);
        c[15] = fmaf(ak, b3.w, c[15]);
    }
}

__global__ void __launch_bounds__(NTHREADS)
ham_kernel(const float* __restrict__ mu, const float* __restrict__ Sigma,
           const float* __restrict__ phi, const float* __restrict__ pi_mu,
           const float* __restrict__ pi_Sigma, const float* __restrict__ pi_phi,
           const float* __restrict__ M_inv,
           float* __restrict__ mu_o, float* __restrict__ Sig_o,
           float* __restrict__ phi_o) {
    __shared__ __align__(16) float smem[PTS_PER_BLK * 256];
    const int tid = threadIdx.x;
    const int lp = tid >> 4;   // local point
    const int r = tid & 15;    // row owned by this thread
    const int p = blockIdx.x * PTS_PER_BLK + lp;
    float* Bs = smem + lp * 256;

    // ---- load Sigma row and pi_Sigma row into registers ----
    float S[16], P[16];
    {
        const float4* sg = (const float4*)(Sigma + (size_t)p * 256 + r * 16);
        const float4* pg = (const float4*)(pi_Sigma + (size_t)p * 256 + r * 16);
#pragma unroll
        for (int i = 0; i < 4; i++) {
            float4 v = sg[i];
            S[4 * i + 0] = v.x; S[4 * i + 1] = v.y;
            S[4 * i + 2] = v.z; S[4 * i + 3] = v.w;
            float4 w = pg[i];
            P[4 * i + 0] = w.x; P[4 * i + 1] = w.y;
            P[4 * i + 2] = w.z; P[4 * i + 3] = w.w;
        }
    }

    // ---- mu update: mu + NSTEPS*dt * M_inv @ pi_mu (pi_mu is constant) ----
    {
        const float* Mr = M_inv + (size_t)p * 256 + r * 16;
        const float* pm = pi_mu + (size_t)p * 16;
        float acc = 0.0f;
#pragma unroll
        for (int j = 0; j < 16; j++) acc = fmaf(Mr[j], pm[j], acc);
        mu_o[(size_t)p * 16 + r] =
            mu[(size_t)p * 16 + r] + ((float)NSTEPS * DT) * acc;
    }

    // ---- phi update (lane 0 of each point, scalar) ----
    if (r == 0) {
        float px = phi[p * 3 + 0], py = phi[p * 3 + 1], pz = phi[p * 3 + 2];
        const float vx = pi_phi[p * 3 + 0];
        const float vy = pi_phi[p * 3 + 1];
        const float vz = pi_phi[p * 3 + 2];
        const float TWO_PI = 6.283185307179586f;
        const float PI_F = 3.141592653589793f;
        const float R_MAX = 3.131592653589793f;  // pi - 0.01
#pragma unroll 1
        for (int s = 0; s < NSTEPS; s++) {
            px += DT * vx; py += DT * vy; pz += DT * vz;
            float th = sqrtf(px * px + py * py + pz * pz);
            float ths = fmaxf(th, 1e-12f);
            float inv = 1.0f / ths;
            float ax = px * inv, ay = py * inv, az = pz * inv;
            float tw = fmodf(th, TWO_PI);
            bool flip = tw > PI_F;
            float tf = flip ? (TWO_PI - tw) : tw;
            if (flip) { ax = -ax; ay = -ay; az = -az; }
            tf = fminf(tf, R_MAX);
            px = ax * tf; py = ay * tf; pz = az * tf;
        }
        phi_o[p * 3 + 0] = px;
        phi_o[p * 3 + 1] = py;
        phi_o[p * 3 + 2] = pz;
    }

    // Taylor coefficients for degree-8 exp
    const float b1 = 1.0f, b2 = 0.5f, b3 = 1.0f / 6.0f, b4 = 1.0f / 24.0f;
    const float b5 = 1.0f / 120.0f, b6 = 1.0f / 720.0f;
    const float b7 = 1.0f / 5040.0f, b8 = 1.0f / 40320.0f;

#pragma unroll 1
    for (int step = 0; step < NSTEPS; step++) {
        // ================= kick 1: P = sym(P - dt * P S P) =================
        float G[16], Q[16], T[16];
        put_row(Bs, r, S);
#pragma unroll
        for (int j = 0; j < 16; j++) G[j] = 0.0f;
        mm16(G, P, Bs);  // G = P*S
        put_row(Bs, r, P);
#pragma unroll
        for (int j = 0; j < 16; j++) Q[j] = 0.0f;
        mm16(Q, G, Bs);  // Q = P*S*P
#pragma unroll
        for (int j = 0; j < 16; j++) T[j] = fmaf(-DT, Q[j], P[j]);
        put_row(Bs, r, T);
#pragma unroll
        for (int j = 0; j < 16; j++) P[j] = 0.5f * (T[j] + Bs[j * 16 + r]);

        // ================= drift: Sigma = sym(Sigma * exp(2dt*P*Sigma)) ====
        // Y = dt*P*S  (= X/2), E = (Taylor8(Y))^2, Sn = S*E
        float Y[16], Y2[16];
        put_row(Bs, r, S);
#pragma unroll
        for (int j = 0; j < 16; j++) Y[j] = 0.0f;
        mm16(Y, P, Bs);  // Y = P*S
#pragma unroll
        for (int j = 0; j < 16; j++) Y[j] *= DT;
        put_row(Bs, r, Y);
#pragma unroll
        for (int j = 0; j < 16; j++) Y2[j] = 0.0f;
        mm16(Y2, Y, Bs);  // Y2 = Y*Y
        float Y3[16];
#pragma unroll
        for (int j = 0; j < 16; j++) Y3[j] = 0.0f;
        mm16(Y3, Y2, Bs);  // Y3 = Y2*Y
        put_row(Bs, r, Y3);  // Bs holds Y3 for the next two matmuls

        // T2 = c2*Y3 + c1,  c2 = b6 I + b7 Y + b8 Y2,  c1 = b3 I + b4 Y + b5 Y2
        float T2[16];
#pragma unroll
        for (int j = 0; j < 16; j++) T2[j] = fmaf(b4, Y[j], b5 * Y2[j]);
        T2[r] += b3;
#pragma unroll
        for (int k = 0; k < 16; k++) {
            float ak = fmaf(b7, Y[k], b8 * Y2[k]);
            if (k == r) ak += b6;
            float4 c0v = *(const float4*)(Bs + k * 16 + 0);
            float4 c1v = *(const float4*)(Bs + k * 16 + 4);
            float4 c2v = *(const float4*)(Bs + k * 16 + 8);
            float4 c3v = *(const float4*)(Bs + k * 16 + 12);
            T2[0]  = fmaf(ak, c0v.x, T2[0]);
            T2[1]  = fmaf(ak, c0v.y, T2[1]);
            T2[2]  = fmaf(ak, c0v.z, T2[2]);
            T2[3]  = fmaf(ak, c0v.w, T2[3]);
            T2[4]  = fmaf(ak, c1v.x, T2[4]);
            T2[5]  = fmaf(ak, c1v.y, T2[5]);
            T2[6]  = fmaf(ak, c1v.z, T2[6]);
            T2[7]  = fmaf(ak, c1v.w, T2[7]);
            T2[8]  = fmaf(ak, c2v.x, T2[8]);
            T2[9]  = fmaf(ak, c2v.y, T2[9]);
            T2[10] = fmaf(ak, c2v.z, T2[10]);
            T2[11] = fmaf(ak, c2v.w, T2[11]);
            T2[12] = fmaf(ak, c3v.x, T2[12]);
            T2[13] = fmaf(ak, c3v.y, T2[13]);
            T2[14] = fmaf(ak, c3v.z, T2[14]);
            T2[15] = fmaf(ak, c3v.w, T2[15]);
        }
        // Pm = T2*Y3 + c0,  c0 = I + b1 Y + b2 Y2   (Bs still holds Y3)
        float Pm[16];
#pragma unroll
        for (int j = 0; j < 16; j++) Pm[j] = fmaf(b1, Y[j], b2 * Y2[j]);
        Pm[r] += 1.0f;
        mm16(Pm, T2, Bs);

        // E = Pm*Pm (undo the X/2 halving)
        float E[16];
        put_row(Bs, r, Pm);
#pragma unroll
        for (int j = 0; j < 16; j++) E[j] = 0.0f;
        mm16(E, Pm, Bs);

        // Sn = S*E; S = sym(Sn) + eps I
        float Sn[16];
        put_row(Bs, r, E);
#pragma unroll
        for (int j = 0; j < 16; j++) Sn[j] = 0.0f;
        mm16(Sn, S, Bs);
        put_row(Bs, r, Sn);
#pragma unroll
        for (int j = 0; j < 16; j++) S[j] = 0.5f * (Sn[j] + Bs[j * 16 + r]);
        S[r] += 1e-8f;

        // ================= kick 2: P = sym(P - dt * P S P) =================
        put_row(Bs, r, S);
#pragma unroll
        for (int j = 0; j < 16; j++) G[j] = 0.0f;
        mm16(G, P, Bs);
        put_row(Bs, r, P);
#pragma unroll
        for (int j = 0; j < 16; j++) Q[j] = 0.0f;
        mm16(Q, G, Bs);
#pragma unroll
        for (int j = 0; j < 16; j++) T[j] = fmaf(-DT, Q[j], P[j]);
        put_row(Bs, r, T);
#pragma unroll
        for (int j = 0; j < 16; j++) P[j] = 0.5f * (T[j] + Bs[j * 16 + r]);
    }

    // ---- store Sigma ----
    {
        float4* so = (float4*)(Sig_o + (size_t)p * 256 + r * 16);
        so[0] = make_float4(S[0], S[1], S[2], S[3]);
        so[1] = make_float4(S[4], S[5], S[6], S[7]);
        so[2] = make_float4(S[8], S[9], S[10], S[11]);
        so[3] = make_float4(S[12], S[13], S[14], S[15]);
    }
}

extern "C" void kernel_launch(void* const* d_in, const int* in_sizes, int n_in,
                              void* d_out, int out_size) {
    const float* mu       = (const float*)d_in[0];
    const float* Sigma    = (const float*)d_in[1];
    const float* phi      = (const float*)d_in[2];
    const float* pi_mu    = (const float*)d_in[3];
    const float* pi_Sigma = (const float*)d_in[4];
    const float* pi_phi   = (const float*)d_in[5];
    const float* M_inv    = (const float*)d_in[6];

    const int npts = in_sizes[0] / 16;  // B*N = 32768
    float* out = (float*)d_out;
    float* mu_o  = out;
    float* Sig_o = out + (size_t)npts * 16;
    float* phi_o = out + (size_t)npts * 16 + (size_t)npts * 256;

    dim3 grid(npts / PTS_PER_BLK);
    dim3 block(NTHREADS);
    ham_kernel<<<grid, block>>>(mu, Sigma, phi, pi_mu, pi_Sigma, pi_phi, M_inv,
                                mu_o, Sig_o, phi_o);
}

// round 2
// speedup vs baseline: 1.3259x; 1.3259x over previous
#include <cuda_runtime.h>
#include <math.h>

#define DT 0.05f
#define NSTEPS 4
#define PTS_PER_BLK 16
#define NTHREADS 256
#define TILE 264  // 256 + 8 pad: kills 2-way bank conflict between the two
                  // points sharing a warp (256 % 32 == 0 was the bug)

__device__ __forceinline__ void put_row(float* Bs, int r, const float v[16]) {
    __syncwarp();
    float4* d = (float4*)(Bs + r * 16);
    d[0] = make_float4(v[0], v[1], v[2], v[3]);
    d[1] = make_float4(v[4], v[5], v[6], v[7]);
    d[2] = make_float4(v[8], v[9], v[10], v[11]);
    d[3] = make_float4(v[12], v[13], v[14], v[15]);
    __syncwarp();
}

// c += a_row * B   (accumulates; caller initializes c)
__device__ __forceinline__ void mm16(float c[16], const float a[16],
                                     const float* Bs) {
#pragma unroll
    for (int k = 0; k < 16; k++) {
        float ak = a[k];
        float4 b0 = *(const float4*)(Bs + k * 16 + 0);
        float4 b1 = *(const float4*)(Bs + k * 16 + 4);
        float4 b2 = *(const float4*)(Bs + k * 16 + 8);
        float4 b3 = *(const float4*)(Bs + k * 16 + 12);
        c[0]  = fmaf(ak, b0.x, c[0]);
        c[1]  = fmaf(ak, b0.y, c[1]);
        c[2]  = fmaf(ak, b0.z, c[2]);
        c[3]  = fmaf(ak, b0.w, c[3]);
        c[4]  = fmaf(ak, b1.x, c[4]);
        c[5]  = fmaf(ak, b1.y, c[5]);
        c[6]  = fmaf(ak, b1.z, c[6]);
        c[7]  = fmaf(ak, b1.w, c[7]);
        c[8]  = fmaf(ak, b2.x, c[8]);
        c[9]  = fmaf(ak, b2.y, c[9]);
        c[10] = fmaf(ak, b2.z, c[10]);
        c[11] = fmaf(ak, b2.w, c[11]);
        c[12] = fmaf(ak, b3.x, c[12]);
        c[13] = fmaf(ak, b3.y, c[13]);
        c[14] = fmaf(ak, b3.z, c[14]);
        c[15] = fmaf(ak, b3.w, c[15]);
    }
}

__global__ void __launch_bounds__(NTHREADS, 2)
ham_kernel(const float* __restrict__ mu, const float* __restrict__ Sigma,
           const float* __restrict__ phi, const float* __restrict__ pi_mu,
           const float* __restrict__ pi_Sigma, const float* __restrict__ pi_phi,
           const float* __restrict__ M_inv,
           float* __restrict__ mu_o, float* __restrict__ Sig_o,
           float* __restrict__ phi_o) {
    __shared__ __align__(16) float smem[PTS_PER_BLK * TILE];
    const int tid = threadIdx.x;
    const int lp = tid >> 4;   // local point
    const int r = tid & 15;    // row owned by this thread
    const int p = blockIdx.x * PTS_PER_BLK + lp;
    float* Bs = smem + lp * TILE;

    // ---- load Sigma row and pi_Sigma row into registers ----
    float S[16], P[16];
    {
        const float4* sg = (const float4*)(Sigma + (size_t)p * 256 + r * 16);
        const float4* pg = (const float4*)(pi_Sigma + (size_t)p * 256 + r * 16);
#pragma unroll
        for (int i = 0; i < 4; i++) {
            float4 v = sg[i];
            S[4 * i + 0] = v.x; S[4 * i + 1] = v.y;
            S[4 * i + 2] = v.z; S[4 * i + 3] = v.w;
            float4 w = pg[i];
            P[4 * i + 0] = w.x; P[4 * i + 1] = w.y;
            P[4 * i + 2] = w.z; P[4 * i + 3] = w.w;
        }
    }

    // ---- mu update: mu + NSTEPS*dt * M_inv @ pi_mu (pi_mu constant) ----
    {
        const float* Mr = M_inv + (size_t)p * 256 + r * 16;
        const float* pm = pi_mu + (size_t)p * 16;
        float acc = 0.0f;
#pragma unroll
        for (int j = 0; j < 16; j++) acc = fmaf(Mr[j], pm[j], acc);
        mu_o[(size_t)p * 16 + r] =
            mu[(size_t)p * 16 + r] + ((float)NSTEPS * DT) * acc;
    }

    // ---- phi update (lane 0 of each point) ----
    if (r == 0) {
        float px = phi[p * 3 + 0], py = phi[p * 3 + 1], pz = phi[p * 3 + 2];
        const float vx = pi_phi[p * 3 + 0];
        const float vy = pi_phi[p * 3 + 1];
        const float vz = pi_phi[p * 3 + 2];
        const float TWO_PI = 6.283185307179586f;
        const float PI_F = 3.141592653589793f;
        const float R_MAX = 3.131592653589793f;
#pragma unroll 1
        for (int s = 0; s < NSTEPS; s++) {
            px += DT * vx; py += DT * vy; pz += DT * vz;
            float th = sqrtf(px * px + py * py + pz * pz);
            float ths = fmaxf(th, 1e-12f);
            float inv = 1.0f / ths;
            float ax = px * inv, ay = py * inv, az = pz * inv;
            float tw = fmodf(th, TWO_PI);
            bool flip = tw > PI_F;
            float tf = flip ? (TWO_PI - tw) : tw;
            if (flip) { ax = -ax; ay = -ay; az = -az; }
            tf = fminf(tf, R_MAX);
            px = ax * tf; py = ay * tf; pz = az * tf;
        }
        phi_o[p * 3 + 0] = px;
        phi_o[p * 3 + 1] = py;
        phi_o[p * 3 + 2] = pz;
    }

    // Taylor deg-6 coefficients (no scaling/squaring; ||X|| ~ 0.28)
    const float b2 = 0.5f, b3 = 1.0f / 6.0f, b4 = 1.0f / 24.0f;
    const float b5 = 1.0f / 120.0f, b6 = 1.0f / 720.0f;

    float X[16], X2[16], C[16];

#pragma unroll 1
    for (int step = 0; step < NSTEPS; step++) {
        // ===== kick 1: P -= dt * P S P  (exactly symmetric; skip sym) =====
        put_row(Bs, r, S);
#pragma unroll
        for (int j = 0; j < 16; j++) X[j] = 0.0f;
        mm16(X, P, Bs);                       // X = P*S
#pragma unroll
        for (int j = 0; j < 16; j++) X[j] *= -DT;   // X = -dt*P*S
        put_row(Bs, r, P);
        mm16(P, X, Bs);                       // P += (-dt*P*S)*P_old

        // ===== drift: S = S * expm(2dt*P*S), deg-6 Paterson-Stockmeyer ====
        put_row(Bs, r, S);
#pragma unroll
        for (int j = 0; j < 16; j++) X[j] = 0.0f;
        mm16(X, P, Bs);                       // X = P*S
#pragma unroll
        for (int j = 0; j < 16; j++) X[j] *= 2.0f * DT;  // X = 2dt*P*S
        put_row(Bs, r, X);
#pragma unroll
        for (int j = 0; j < 16; j++) X2[j] = 0.0f;
        mm16(X2, X, Bs);                      // X2 = X*X
#pragma unroll
        for (int j = 0; j < 16; j++) C[j] = 0.0f;
        mm16(C, X2, Bs);                      // C = X3 = X2*X  (Bs still X)
        put_row(Bs, r, C);                    // shared <- X3
        // A-operand: C = b6*X3 + b5*X2 + b4*X + b3*I  (in place)
#pragma unroll
        for (int j = 0; j < 16; j++)
            C[j] = fmaf(b6, C[j], fmaf(b5, X2[j], b4 * X[j]));
        C[r] += b3;
        // accumulator: X = A0 = I + X + 0.5*X2
#pragma unroll
        for (int j = 0; j < 16; j++) X[j] = fmaf(b2, X2[j], X[j]);
        X[r] += 1.0f;
        mm16(X, C, Bs);                       // X = E = A0 + C*X3
        put_row(Bs, r, X);                    // shared <- E
#pragma unroll
        for (int j = 0; j < 16; j++) X2[j] = 0.0f;
        mm16(X2, S, Bs);                      // X2 = S*E = S_new (symmetric)
#pragma unroll
        for (int j = 0; j < 16; j++) S[j] = X2[j];
        S[r] += 1e-8f;

        // ===== kick 2 =====
        put_row(Bs, r, S);
#pragma unroll
        for (int j = 0; j < 16; j++) X[j] = 0.0f;
        mm16(X, P, Bs);
#pragma unroll
        for (int j = 0; j < 16; j++) X[j] *= -DT;
        put_row(Bs, r, P);
        mm16(P, X, Bs);
    }

    // ---- final symmetrize of Sigma (cheap, once) + store ----
    put_row(Bs, r, S);
#pragma unroll
    for (int j = 0; j < 16; j++) S[j] = 0.5f * (S[j] + Bs[j * 16 + r]);
    {
        float4* so = (float4*)(Sig_o + (size_t)p * 256 + r * 16);
        so[0] = make_float4(S[0], S[1], S[2], S[3]);
        so[1] = make_float4(S[4], S[5], S[6], S[7]);
        so[2] = make_float4(S[8], S[9], S[10], S[11]);
        so[3] = make_float4(S[12], S[13], S[14], S[15]);
    }
}

extern "C" void kernel_launch(void* const* d_in, const int* in_sizes, int n_in,
                              void* d_out, int out_size) {
    const float* mu       = (const float*)d_in[0];
    const float* Sigma    = (const float*)d_in[1];
    const float* phi      = (const float*)d_in[2];
    const float* pi_mu    = (const float*)d_in[3];
    const float* pi_Sigma = (const float*)d_in[4];
    const float* pi_phi   = (const float*)d_in[5];
    const float* M_inv    = (const float*)d_in[6];

    const int npts = in_sizes[0] / 16;  // B*N = 32768
    float* out = (float*)d_out;
    float* mu_o  = out;
    float* Sig_o = out + (size_t)npts * 16;
    float* phi_o = out + (size_t)npts * 16 + (size_t)npts * 256;

    dim3 grid(npts / PTS_PER_BLK);
    dim3 block(NTHREADS);
    ham_kernel<<<grid, block>>>(mu, Sigma, phi, pi_mu, pi_Sigma, pi_phi, M_inv,
                                mu_o, Sig_o, phi_o);
}

// round 3
// speedup vs baseline: 1.3620x; 1.0272x over previous
#include <cuda_runtime.h>
#include <math.h>

#define DT 0.05f
#define NSTEPS 4
#define PTS_PER_BLK 16
#define NTHREADS 256
#define TILE 264  // 256 + 8 pad: conflict-free between the two points/warp

typedef unsigned long long u64;

__device__ __forceinline__ u64 pack2(float x, float y) {
    u64 r;
    asm("mov.b64 %0, {%1, %2};" : "=l"(r) : "f"(x), "f"(y));
    return r;
}
__device__ __forceinline__ void unpack2(u64 v, float& x, float& y) {
    asm("mov.b64 {%0, %1}, %2;" : "=f"(x), "=f"(y) : "l"(v));
}
__device__ __forceinline__ void fma2(u64& d, u64 a, u64 b) {
    asm("fma.rn.f32x2 %0, %1, %2, %0;" : "+l"(d) : "l"(a), "l"(b));
}

__device__ __forceinline__ void put_row(float* Bs, int r, const float v[16]) {
    __syncwarp();
    float4* d = (float4*)(Bs + r * 16);
    d[0] = make_float4(v[0], v[1], v[2], v[3]);
    d[1] = make_float4(v[4], v[5], v[6], v[7]);
    d[2] = make_float4(v[8], v[9], v[10], v[11]);
    d[3] = make_float4(v[12], v[13], v[14], v[15]);
    __syncwarp();
}

// c += a_row * B  using packed f32x2 FMAs (B = 16x16 tile in shared)
__device__ __forceinline__ void mm16(float c[16], const float a[16],
                                     const float* Bs) {
    u64 acc[8];
#pragma unroll
    for (int i = 0; i < 8; i++) acc[i] = pack2(c[2 * i], c[2 * i + 1]);
#pragma unroll
    for (int k = 0; k < 16; k++) {
        u64 ak = pack2(a[k], a[k]);
        const ulonglong2* bp = (const ulonglong2*)(Bs + k * 16);
        ulonglong2 b0 = bp[0];
        ulonglong2 b1 = bp[1];
        ulonglong2 b2 = bp[2];
        ulonglong2 b3 = bp[3];
        fma2(acc[0], ak, b0.x);
        fma2(acc[1], ak, b0.y);
        fma2(acc[2], ak, b1.x);
        fma2(acc[3], ak, b1.y);
        fma2(acc[4], ak, b2.x);
        fma2(acc[5], ak, b2.y);
        fma2(acc[6], ak, b3.x);
        fma2(acc[7], ak, b3.y);
    }
#pragma unroll
    for (int i = 0; i < 8; i++) unpack2(acc[i], c[2 * i], c[2 * i + 1]);
}

__global__ void __launch_bounds__(NTHREADS, 2)
ham_kernel(const float* __restrict__ mu, const float* __restrict__ Sigma,
           const float* __restrict__ phi, const float* __restrict__ pi_mu,
           const float* __restrict__ pi_Sigma, const float* __restrict__ pi_phi,
           const float* __restrict__ M_inv,
           float* __restrict__ mu_o, float* __restrict__ Sig_o,
           float* __restrict__ phi_o) {
    __shared__ __align__(16) float smem[PTS_PER_BLK * TILE];
    const int tid = threadIdx.x;
    const int lp = tid >> 4;   // local point
    const int r = tid & 15;    // row owned by this thread
    const int p = blockIdx.x * PTS_PER_BLK + lp;
    float* Bs = smem + lp * TILE;

    // ---- load Sigma row and pi_Sigma row into registers ----
    float S[16], P[16];
    {
        const float4* sg = (const float4*)(Sigma + (size_t)p * 256 + r * 16);
        const float4* pg = (const float4*)(pi_Sigma + (size_t)p * 256 + r * 16);
#pragma unroll
        for (int i = 0; i < 4; i++) {
            float4 v = sg[i];
            S[4 * i + 0] = v.x; S[4 * i + 1] = v.y;
            S[4 * i + 2] = v.z; S[4 * i + 3] = v.w;
            float4 w = pg[i];
            P[4 * i + 0] = w.x; P[4 * i + 1] = w.y;
            P[4 * i + 2] = w.z; P[4 * i + 3] = w.w;
        }
    }

    // ---- mu update: mu + NSTEPS*dt * M_inv @ pi_mu (pi_mu constant) ----
    {
        const float* Mr = M_inv + (size_t)p * 256 + r * 16;
        const float* pm = pi_mu + (size_t)p * 16;
        float acc = 0.0f;
#pragma unroll
        for (int j = 0; j < 16; j++) acc = fmaf(Mr[j], pm[j], acc);
        mu_o[(size_t)p * 16 + r] =
            mu[(size_t)p * 16 + r] + ((float)NSTEPS * DT) * acc;
    }

    // ---- phi update (lane 0 of each point) ----
    if (r == 0) {
        float px = phi[p * 3 + 0], py = phi[p * 3 + 1], pz = phi[p * 3 + 2];
        const float vx = pi_phi[p * 3 + 0];
        const float vy = pi_phi[p * 3 + 1];
        const float vz = pi_phi[p * 3 + 2];
        const float TWO_PI = 6.283185307179586f;
        const float PI_F = 3.141592653589793f;
        const float R_MAX = 3.131592653589793f;
#pragma unroll 1
        for (int s = 0; s < NSTEPS; s++) {
            px += DT * vx; py += DT * vy; pz += DT * vz;
            float th = sqrtf(px * px + py * py + pz * pz);
            float ths = fmaxf(th, 1e-12f);
            float inv = 1.0f / ths;
            float ax = px * inv, ay = py * inv, az = pz * inv;
            float tw = fmodf(th, TWO_PI);
            bool flip = tw > PI_F;
            float tf = flip ? (TWO_PI - tw) : tw;
            if (flip) { ax = -ax; ay = -ay; az = -az; }
            tf = fminf(tf, R_MAX);
            px = ax * tf; py = ay * tf; pz = az * tf;
        }
        phi_o[p * 3 + 0] = px;
        phi_o[p * 3 + 1] = py;
        phi_o[p * 3 + 2] = pz;
    }

    // Taylor deg-6 coefficients (no scaling/squaring; ||X|| ~ 0.28)
    const float b2 = 0.5f, b3 = 1.0f / 6.0f, b4 = 1.0f / 24.0f;
    const float b5 = 1.0f / 120.0f, b6 = 1.0f / 720.0f;

    float X[16], X2[16], C[16];

#pragma unroll 1
    for (int step = 0; step < NSTEPS; step++) {
        // ===== kick 1: P -= dt * P S P  (exactly symmetric) =====
        put_row(Bs, r, S);
#pragma unroll
        for (int j = 0; j < 16; j++) X[j] = 0.0f;
        mm16(X, P, Bs);                       // X = P*S
#pragma unroll
        for (int j = 0; j < 16; j++) X[j] *= -DT;   // X = -dt*P*S
        put_row(Bs, r, P);
        mm16(P, X, Bs);                       // P += (-dt*P*S)*P_old

        // ===== drift: S = S * expm(2dt*P*S), deg-6 Paterson-Stockmeyer ====
        put_row(Bs, r, S);
#pragma unroll
        for (int j = 0; j < 16; j++) X[j] = 0.0f;
        mm16(X, P, Bs);                       // X = P*S
#pragma unroll
        for (int j = 0; j < 16; j++) X[j] *= 2.0f * DT;  // X = 2dt*P*S
        put_row(Bs, r, X);
#pragma unroll
        for (int j = 0; j < 16; j++) X2[j] = 0.0f;
        mm16(X2, X, Bs);                      // X2 = X*X
#pragma unroll
        for (int j = 0; j < 16; j++) C[j] = 0.0f;
        mm16(C, X2, Bs);                      // C = X3 = X2*X  (Bs still X)
        put_row(Bs, r, C);                    // shared <- X3
        // A-operand: C = b6*X3 + b5*X2 + b4*X + b3*I
#pragma unroll
        for (int j = 0; j < 16; j++)
            C[j] = fmaf(b6, C[j], fmaf(b5, X2[j], b4 * X[j]));
        C[r] += b3;
        // accumulator: X = A0 = I + X + 0.5*X2
#pragma unroll
        for (int j = 0; j < 16; j++) X[j] = fmaf(b2, X2[j], X[j]);
        X[r] += 1.0f;
        mm16(X, C, Bs);                       // X = E = A0 + C*X3
        put_row(Bs, r, X);                    // shared <- E
#pragma unroll
        for (int j = 0; j < 16; j++) X2[j] = 0.0f;
        mm16(X2, S, Bs);                      // X2 = S*E = S_new (symmetric)
#pragma unroll
        for (int j = 0; j < 16; j++) S[j] = X2[j];
        S[r] += 1e-8f;

        // ===== kick 2 =====
        put_row(Bs, r, S);
#pragma unroll
        for (int j = 0; j < 16; j++) X[j] = 0.0f;
        mm16(X, P, Bs);
#pragma unroll
        for (int j = 0; j < 16; j++) X[j] *= -DT;
        put_row(Bs, r, P);
        mm16(P, X, Bs);
    }

    // ---- final symmetrize of Sigma (cheap, once) + store ----
    put_row(Bs, r, S);
#pragma unroll
    for (int j = 0; j < 16; j++) S[j] = 0.5f * (S[j] + Bs[j * 16 + r]);
    {
        float4* so = (float4*)(Sig_o + (size_t)p * 256 + r * 16);
        so[0] = make_float4(S[0], S[1], S[2], S[3]);
        so[1] = make_float4(S[4], S[5], S[6], S[7]);
        so[2] = make_float4(S[8], S[9], S[10], S[11]);
        so[3] = make_float4(S[12], S[13], S[14], S[15]);
    }
}

extern "C" void kernel_launch(void* const* d_in, const int* in_sizes, int n_in,
                              void* d_out, int out_size) {
    const float* mu       = (const float*)d_in[0];
    const float* Sigma    = (const float*)d_in[1];
    const float* phi      = (const float*)d_in[2];
    const float* pi_mu    = (const float*)d_in[3];
    const float* pi_Sigma = (const float*)d_in[4];
    const float* pi_phi   = (const float*)d_in[5];
    const float* M_inv    = (const float*)d_in[6];

    const int npts = in_sizes[0] / 16;  // B*N = 32768
    float* out = (float*)d_out;
    float* mu_o  = out;
    float* Sig_o = out + (size_t)npts * 16;
    float* phi_o = out + (size_t)npts * 16 + (size_t)npts * 256;

    dim3 grid(npts / PTS_PER_BLK);
    dim3 block(NTHREADS);
    ham_kernel<<<grid, block>>>(mu, Sigma, phi, pi_mu, pi_Sigma, pi_phi, M_inv,
                                mu_o, Sig_o, phi_o);
}

// round 4
// speedup vs baseline: 1.7928x; 1.3163x over previous
#include <cuda_runtime.h>
#include <math.h>

#define DT 0.05f
#define NSTEPS 4
#define NTHREADS 256
#define PTS 32          // points per block (8 threads each)
#define TSTR 20         // tile row stride in floats (conflict-free, 16B aligned)
#define PPB 900         // floats per point: tile 320 + S 256... (320+256+256=832->pad)
#define TILE_OFF 0
#define S_OFF 320
#define P_OFF 640
#define SMEM_BYTES (PTS * PPB * 4)

typedef unsigned long long u64;

__device__ __forceinline__ u64 pack2(float x, float y) {
    u64 r;
    asm("mov.b64 %0, {%1, %2};" : "=l"(r) : "f"(x), "f"(y));
    return r;
}
__device__ __forceinline__ void unpack2(u64 v, float& x, float& y) {
    asm("mov.b64 {%0, %1}, %2;" : "=f"(x), "=f"(y) : "l"(v));
}
__device__ __forceinline__ void fma2(u64& d, u64 a, u64 b) {
    asm("fma.rn.f32x2 %0, %1, %2, %0;" : "+l"(d) : "l"(a), "l"(b));
}

// Write this thread's two rows (q, q+8) into the stride-TSTR tile.
__device__ __forceinline__ void put2(float* tile, int q, const float v0[16],
                                     const float v1[16]) {
    __syncwarp();
    float4* d0 = (float4*)(tile + q * TSTR);
    float4* d1 = (float4*)(tile + (q + 8) * TSTR);
    d0[0] = make_float4(v0[0], v0[1], v0[2], v0[3]);
    d0[1] = make_float4(v0[4], v0[5], v0[6], v0[7]);
    d0[2] = make_float4(v0[8], v0[9], v0[10], v0[11]);
    d0[3] = make_float4(v0[12], v0[13], v0[14], v0[15]);
    d1[0] = make_float4(v1[0], v1[1], v1[2], v1[3]);
    d1[1] = make_float4(v1[4], v1[5], v1[6], v1[7]);
    d1[2] = make_float4(v1[8], v1[9], v1[10], v1[11]);
    d1[3] = make_float4(v1[12], v1[13], v1[14], v1[15]);
    __syncwarp();
}

// c{0,1} = a{0,1} * B   (zero-init accumulators)
template <int BSTR>
__device__ __forceinline__ void mm2z(float c0[16], float c1[16],
                                     const float a0[16], const float a1[16],
                                     const float* Bs) {
    u64 acc0[8], acc1[8];
#pragma unroll
    for (int i = 0; i < 8; i++) { acc0[i] = 0ULL; acc1[i] = 0ULL; }
#pragma unroll
    for (int k = 0; k < 16; k++) {
        const ulonglong2* bp = (const ulonglong2*)(Bs + k * BSTR);
        ulonglong2 ba = bp[0], bb = bp[1], bc = bp[2], bd = bp[3];
        u64 ak0 = pack2(a0[k], a0[k]);
        u64 ak1 = pack2(a1[k], a1[k]);
        fma2(acc0[0], ak0, ba.x); fma2(acc0[1], ak0, ba.y);
        fma2(acc0[2], ak0, bb.x); fma2(acc0[3], ak0, bb.y);
        fma2(acc0[4], ak0, bc.x); fma2(acc0[5], ak0, bc.y);
        fma2(acc0[6], ak0, bd.x); fma2(acc0[7], ak0, bd.y);
        fma2(acc1[0], ak1, ba.x); fma2(acc1[1], ak1, ba.y);
        fma2(acc1[2], ak1, bb.x); fma2(acc1[3], ak1, bb.y);
        fma2(acc1[4], ak1, bc.x); fma2(acc1[5], ak1, bc.y);
        fma2(acc1[6], ak1, bd.x); fma2(acc1[7], ak1, bd.y);
    }
#pragma unroll
    for (int i = 0; i < 8; i++) {
        unpack2(acc0[i], c0[2 * i], c0[2 * i + 1]);
        unpack2(acc1[i], c1[2 * i], c1[2 * i + 1]);
    }
}

// c{0,1} += a{0,1} * B
template <int BSTR>
__device__ __forceinline__ void mm2a(float c0[16], float c1[16],
                                     const float a0[16], const float a1[16],
                                     const float* Bs) {
    u64 acc0[8], acc1[8];
#pragma unroll
    for (int i = 0; i < 8; i++) {
        acc0[i] = pack2(c0[2 * i], c0[2 * i + 1]);
        acc1[i] = pack2(c1[2 * i], c1[2 * i + 1]);
    }
#pragma unroll
    for (int k = 0; k < 16; k++) {
        const ulonglong2* bp = (const ulonglong2*)(Bs + k * BSTR);
        ulonglong2 ba = bp[0], bb = bp[1], bc = bp[2], bd = bp[3];
        u64 ak0 = pack2(a0[k], a0[k]);
        u64 ak1 = pack2(a1[k], a1[k]);
        fma2(acc0[0], ak0, ba.x); fma2(acc0[1], ak0, ba.y);
        fma2(acc0[2], ak0, bb.x); fma2(acc0[3], ak0, bb.y);
        fma2(acc0[4], ak0, bc.x); fma2(acc0[5], ak0, bc.y);
        fma2(acc0[6], ak0, bd.x); fma2(acc0[7], ak0, bd.y);
        fma2(acc1[0], ak1, ba.x); fma2(acc1[1], ak1, ba.y);
        fma2(acc1[2], ak1, bb.x); fma2(acc1[3], ak1, bb.y);
        fma2(acc1[4], ak1, bc.x); fma2(acc1[5], ak1, bc.y);
        fma2(acc1[6], ak1, bd.x); fma2(acc1[7], ak1, bd.y);
    }
#pragma unroll
    for (int i = 0; i < 8; i++) {
        unpack2(acc0[i], c0[2 * i], c0[2 * i + 1]);
        unpack2(acc1[i], c1[2 * i], c1[2 * i + 1]);
    }
}

__device__ __forceinline__ void ld_row16(float v[16], const float* src) {
    const float4* s = (const float4*)src;
#pragma unroll
    for (int i = 0; i < 4; i++) {
        float4 t = s[i];
        v[4 * i + 0] = t.x; v[4 * i + 1] = t.y;
        v[4 * i + 2] = t.z; v[4 * i + 3] = t.w;
    }
}
__device__ __forceinline__ void st_row16(float* dst, const float v[16]) {
    float4* d = (float4*)dst;
    d[0] = make_float4(v[0], v[1], v[2], v[3]);
    d[1] = make_float4(v[4], v[5], v[6], v[7]);
    d[2] = make_float4(v[8], v[9], v[10], v[11]);
    d[3] = make_float4(v[12], v[13], v[14], v[15]);
}

__global__ void __launch_bounds__(NTHREADS, 2)
ham_kernel(const float* __restrict__ mu, const float* __restrict__ Sigma,
           const float* __restrict__ phi, const float* __restrict__ pi_mu,
           const float* __restrict__ pi_Sigma, const float* __restrict__ pi_phi,
           const float* __restrict__ M_inv,
           float* __restrict__ mu_o, float* __restrict__ Sig_o,
           float* __restrict__ phi_o) {
    extern __shared__ float smem[];
    const int tid = threadIdx.x;
    const int lp = tid >> 3;   // local point 0..31
    const int q = tid & 7;     // owns rows q and q+8
    const int r1 = q + 8;
    const int p = blockIdx.x * PTS + lp;
    float* tile = smem + lp * PPB + TILE_OFF;
    float* Ss = smem + lp * PPB + S_OFF;   // stride 16
    float* Ps = smem + lp * PPB + P_OFF;   // stride 16

    // ---- load P rows into regs; S rows into shared stash ----
    float P0[16], P1[16];
    ld_row16(P0, pi_Sigma + (size_t)p * 256 + q * 16);
    ld_row16(P1, pi_Sigma + (size_t)p * 256 + r1 * 16);
    {
        float t0[16], t1[16];
        ld_row16(t0, Sigma + (size_t)p * 256 + q * 16);
        ld_row16(t1, Sigma + (size_t)p * 256 + r1 * 16);
        st_row16(Ss + q * 16, t0);
        st_row16(Ss + r1 * 16, t1);
    }

    // ---- mu update (rows q, q+8): mu + NSTEPS*dt * M_inv @ pi_mu ----
    {
        const float* pm = pi_mu + (size_t)p * 16;
        float pmv[16];
        ld_row16(pmv, pm);
        const float* M0 = M_inv + (size_t)p * 256 + q * 16;
        const float* M1 = M_inv + (size_t)p * 256 + r1 * 16;
        float a0 = 0.0f, a1 = 0.0f;
#pragma unroll
        for (int j = 0; j < 16; j++) {
            a0 = fmaf(M0[j], pmv[j], a0);
            a1 = fmaf(M1[j], pmv[j], a1);
        }
        mu_o[(size_t)p * 16 + q]  = mu[(size_t)p * 16 + q]  + ((float)NSTEPS * DT) * a0;
        mu_o[(size_t)p * 16 + r1] = mu[(size_t)p * 16 + r1] + ((float)NSTEPS * DT) * a1;
    }

    // ---- phi update (thread q==0 of each point) ----
    if (q == 0) {
        float px = phi[p * 3 + 0], py = phi[p * 3 + 1], pz = phi[p * 3 + 2];
        const float vx = pi_phi[p * 3 + 0];
        const float vy = pi_phi[p * 3 + 1];
        const float vz = pi_phi[p * 3 + 2];
        const float TWO_PI = 6.283185307179586f;
        const float PI_F = 3.141592653589793f;
        const float R_MAX = 3.131592653589793f;
#pragma unroll 1
        for (int s = 0; s < NSTEPS; s++) {
            px += DT * vx; py += DT * vy; pz += DT * vz;
            float th = sqrtf(px * px + py * py + pz * pz);
            float ths = fmaxf(th, 1e-12f);
            float inv = 1.0f / ths;
            float ax = px * inv, ay = py * inv, az = pz * inv;
            float tw = fmodf(th, TWO_PI);
            bool flip = tw > PI_F;
            float tf = flip ? (TWO_PI - tw) : tw;
            if (flip) { ax = -ax; ay = -ay; az = -az; }
            tf = fminf(tf, R_MAX);
            px = ax * tf; py = ay * tf; pz = az * tf;
        }
        phi_o[p * 3 + 0] = px;
        phi_o[p * 3 + 1] = py;
        phi_o[p * 3 + 2] = pz;
    }
    __syncwarp();

    float X0[16], X1[16], Y0[16], Y1[16], C0[16], C1[16];

    // poly constants against A0 = I + X + 0.5*X2:
    //   C = 0.125*I + (1/24)*A0 - 0.0125*X2 + (1/720)*X3
    const float cA = 1.0f / 24.0f, cI = 0.125f, cY = -0.0125f, cX3 = 1.0f / 720.0f;

#pragma unroll 1
    for (int step = 0; step < NSTEPS; step++) {
        // ===== kick1: P -= dt * P*S*P =====
        mm2z<16>(X0, X1, P0, P1, Ss);            // X = P*S
#pragma unroll
        for (int j = 0; j < 16; j++) { X0[j] *= -DT; X1[j] *= -DT; }
        put2(tile, q, P0, P1);                   // tile <- P
        mm2a<TSTR>(P0, P1, X0, X1, tile);        // P += X*P

        // ===== drift: S <- S * exp(2dt*P*S) (deg-6 PS Taylor) =====
        mm2z<16>(X0, X1, P0, P1, Ss);            // X = P*S
#pragma unroll
        for (int j = 0; j < 16; j++) { X0[j] *= 2.0f * DT; X1[j] *= 2.0f * DT; }
        if (step < NSTEPS - 1) {                 // stash P (kick2 needs it)
            __syncwarp();
            st_row16(Ps + q * 16, P0);
            st_row16(Ps + r1 * 16, P1);
        }
        put2(tile, q, X0, X1);                   // tile <- X
        mm2z<TSTR>(Y0, Y1, X0, X1, tile);        // Y = X^2
        // A0 = I + X + 0.5*X2  (overwrite X)
#pragma unroll
        for (int j = 0; j < 16; j++) {
            X0[j] = fmaf(0.5f, Y0[j], X0[j]);
            X1[j] = fmaf(0.5f, Y1[j], X1[j]);
        }
        X0[q] += 1.0f; X1[r1] += 1.0f;
        mm2z<TSTR>(C0, C1, Y0, Y1, tile);        // C = X^3
        put2(tile, q, C0, C1);                   // tile <- X^3
#pragma unroll
        for (int j = 0; j < 16; j++) {
            C0[j] = fmaf(cX3, C0[j], fmaf(cY, Y0[j], cA * X0[j]));
            C1[j] = fmaf(cX3, C1[j], fmaf(cY, Y1[j], cA * X1[j]));
        }
        C0[q] += cI; C1[r1] += cI;
        mm2a<TSTR>(X0, X1, C0, C1, tile);        // X = E = A0 + C*X^3
        put2(tile, q, X0, X1);                   // tile <- E
        ld_row16(Y0, Ss + q * 16);               // Y = S rows (old S)
        ld_row16(Y1, Ss + r1 * 16);
        mm2z<TSTR>(C0, C1, Y0, Y1, tile);        // C = S*E  (symmetric)
        C0[q] += 1e-8f; C1[r1] += 1e-8f;
        __syncwarp();
        st_row16(Ss + q * 16, C0);               // S stash <- S_new
        st_row16(Ss + r1 * 16, C1);
        __syncwarp();

        // ===== kick2 (dead on final step: P is not an output) =====
        if (step < NSTEPS - 1) {
            ld_row16(P0, Ps + q * 16);
            ld_row16(P1, Ps + r1 * 16);
            mm2z<16>(X0, X1, P0, P1, Ss);        // X = P*S_new
#pragma unroll
            for (int j = 0; j < 16; j++) { X0[j] *= -DT; X1[j] *= -DT; }
            put2(tile, q, P0, P1);
            mm2a<TSTR>(P0, P1, X0, X1, tile);    // P += X*P
        }
    }

    // ---- final symmetrize (transpose via S stash) + store ----
    // C holds S_new rows; Ss holds the full S_new matrix.
#pragma unroll
    for (int j = 0; j < 16; j++) {
        C0[j] = 0.5f * (C0[j] + Ss[j * 16 + q]);
        C1[j] = 0.5f * (C1[j] + Ss[j * 16 + r1]);
    }
    st_row16(Sig_o + (size_t)p * 256 + q * 16, C0);
    st_row16(Sig_o + (size_t)p * 256 + r1 * 16, C1);
}

extern "C" void kernel_launch(void* const* d_in, const int* in_sizes, int n_in,
                              void* d_out, int out_size) {
    const float* mu       = (const float*)d_in[0];
    const float* Sigma    = (const float*)d_in[1];
    const float* phi      = (const float*)d_in[2];
    const float* pi_mu    = (const float*)d_in[3];
    const float* pi_Sigma = (const float*)d_in[4];
    const float* pi_phi   = (const float*)d_in[5];
    const float* M_inv    = (const float*)d_in[6];

    const int npts = in_sizes[0] / 16;  // B*N = 32768
    float* out = (float*)d_out;
    float* mu_o  = out;
    float* Sig_o = out + (size_t)npts * 16;
    float* phi_o = out + (size_t)npts * 16 + (size_t)npts * 256;

    cudaFuncSetAttribute(ham_kernel, cudaFuncAttributeMaxDynamicSharedMemorySize,
                         SMEM_BYTES);

    dim3 grid(npts / PTS);
    dim3 block(NTHREADS);
    ham_kernel<<<grid, block, SMEM_BYTES>>>(mu, Sigma, phi, pi_mu, pi_Sigma,
                                            pi_phi, M_inv, mu_o, Sig_o, phi_o);
}

// round 5
// speedup vs baseline: 2.0473x; 1.1420x over previous
#include <cuda_runtime.h>
#include <math.h>

#define DT 0.05f
#define NSTEPS 4
#define NTHREADS 256
#define PTS 32          // points per block (8 threads each)
#define TSTR 20         // tile row stride (floats): conflict-free, 16B aligned
#define PPB 836         // floats per point (mod 32 == 4 -> bank stagger)
#define TILE_OFF 0      // 320 floats
#define S_OFF 320       // 256 floats
#define P_OFF 576       // 256 floats
#define SMEM_BYTES (PTS * PPB * 4)

typedef unsigned long long u64;

__device__ __forceinline__ u64 pack2(float x, float y) {
    u64 r;
    asm("mov.b64 %0, {%1, %2};" : "=l"(r) : "f"(x), "f"(y));
    return r;
}
__device__ __forceinline__ void unpack2(u64 v, float& x, float& y) {
    asm("mov.b64 {%0, %1}, %2;" : "=f"(x), "=f"(y) : "l"(v));
}
__device__ __forceinline__ void fma2(u64& d, u64 a, u64 b) {
    asm("fma.rn.f32x2 %0, %1, %2, %0;" : "+l"(d) : "l"(a), "l"(b));
}

// Write this thread's two rows (q, q+8) into the stride-TSTR tile.
__device__ __forceinline__ void put2(float* tile, int q, const float v0[16],
                                     const float v1[16]) {
    __syncwarp();
    float4* d0 = (float4*)(tile + q * TSTR);
    float4* d1 = (float4*)(tile + (q + 8) * TSTR);
    d0[0] = make_float4(v0[0], v0[1], v0[2], v0[3]);
    d0[1] = make_float4(v0[4], v0[5], v0[6], v0[7]);
    d0[2] = make_float4(v0[8], v0[9], v0[10], v0[11]);
    d0[3] = make_float4(v0[12], v0[13], v0[14], v0[15]);
    d1[0] = make_float4(v1[0], v1[1], v1[2], v1[3]);
    d1[1] = make_float4(v1[4], v1[5], v1[6], v1[7]);
    d1[2] = make_float4(v1[8], v1[9], v1[10], v1[11]);
    d1[3] = make_float4(v1[12], v1[13], v1[14], v1[15]);
    __syncwarp();
}

// c{0,1} = a{0,1} * B   (zero-init)
template <int BSTR>
__device__ __forceinline__ void mm2z(float c0[16], float c1[16],
                                     const float a0[16], const float a1[16],
                                     const float* Bs) {
    u64 acc0[8], acc1[8];
#pragma unroll
    for (int i = 0; i < 8; i++) { acc0[i] = 0ULL; acc1[i] = 0ULL; }
#pragma unroll
    for (int k = 0; k < 16; k++) {
        const ulonglong2* bp = (const ulonglong2*)(Bs + k * BSTR);
        ulonglong2 ba = bp[0], bb = bp[1], bc = bp[2], bd = bp[3];
        u64 ak0 = pack2(a0[k], a0[k]);
        u64 ak1 = pack2(a1[k], a1[k]);
        fma2(acc0[0], ak0, ba.x); fma2(acc0[1], ak0, ba.y);
        fma2(acc0[2], ak0, bb.x); fma2(acc0[3], ak0, bb.y);
        fma2(acc0[4], ak0, bc.x); fma2(acc0[5], ak0, bc.y);
        fma2(acc0[6], ak0, bd.x); fma2(acc0[7], ak0, bd.y);
        fma2(acc1[0], ak1, ba.x); fma2(acc1[1], ak1, ba.y);
        fma2(acc1[2], ak1, bb.x); fma2(acc1[3], ak1, bb.y);
        fma2(acc1[4], ak1, bc.x); fma2(acc1[5], ak1, bc.y);
        fma2(acc1[6], ak1, bd.x); fma2(acc1[7], ak1, bd.y);
    }
#pragma unroll
    for (int i = 0; i < 8; i++) {
        unpack2(acc0[i], c0[2 * i], c0[2 * i + 1]);
        unpack2(acc1[i], c1[2 * i], c1[2 * i + 1]);
    }
}

// c{0,1} += a{0,1} * B
template <int BSTR>
__device__ __forceinline__ void mm2a(float c0[16], float c1[16],
                                     const float a0[16], const float a1[16],
                                     const float* Bs) {
    u64 acc0[8], acc1[8];
#pragma unroll
    for (int i = 0; i < 8; i++) {
        acc0[i] = pack2(c0[2 * i], c0[2 * i + 1]);
        acc1[i] = pack2(c1[2 * i], c1[2 * i + 1]);
    }
#pragma unroll
    for (int k = 0; k < 16; k++) {
        const ulonglong2* bp = (const ulonglong2*)(Bs + k * BSTR);
        ulonglong2 ba = bp[0], bb = bp[1], bc = bp[2], bd = bp[3];
        u64 ak0 = pack2(a0[k], a0[k]);
        u64 ak1 = pack2(a1[k], a1[k]);
        fma2(acc0[0], ak0, ba.x); fma2(acc0[1], ak0, ba.y);
        fma2(acc0[2], ak0, bb.x); fma2(acc0[3], ak0, bb.y);
        fma2(acc0[4], ak0, bc.x); fma2(acc0[5], ak0, bc.y);
        fma2(acc0[6], ak0, bd.x); fma2(acc0[7], ak0, bd.y);
        fma2(acc1[0], ak1, ba.x); fma2(acc1[1], ak1, ba.y);
        fma2(acc1[2], ak1, bb.x); fma2(acc1[3], ak1, bb.y);
        fma2(acc1[4], ak1, bc.x); fma2(acc1[5], ak1, bc.y);
        fma2(acc1[6], ak1, bd.x); fma2(acc1[7], ak1, bd.y);
    }
#pragma unroll
    for (int i = 0; i < 8; i++) {
        unpack2(acc0[i], c0[2 * i], c0[2 * i + 1]);
        unpack2(acc1[i], c1[2 * i], c1[2 * i + 1]);
    }
}

__device__ __forceinline__ void ld_row16(float v[16], const float* src) {
    const float4* s = (const float4*)src;
#pragma unroll
    for (int i = 0; i < 4; i++) {
        float4 t = s[i];
        v[4 * i + 0] = t.x; v[4 * i + 1] = t.y;
        v[4 * i + 2] = t.z; v[4 * i + 3] = t.w;
    }
}
__device__ __forceinline__ void st_row16(float* dst, const float v[16]) {
    float4* d = (float4*)dst;
    d[0] = make_float4(v[0], v[1], v[2], v[3]);
    d[1] = make_float4(v[4], v[5], v[6], v[7]);
    d[2] = make_float4(v[8], v[9], v[10], v[11]);
    d[3] = make_float4(v[12], v[13], v[14], v[15]);
}

__global__ void __launch_bounds__(NTHREADS, 2)
ham_kernel(const float* __restrict__ mu, const float* __restrict__ Sigma,
           const float* __restrict__ phi, const float* __restrict__ pi_mu,
           const float* __restrict__ pi_Sigma, const float* __restrict__ pi_phi,
           const float* __restrict__ M_inv,
           float* __restrict__ mu_o, float* __restrict__ Sig_o,
           float* __restrict__ phi_o) {
    extern __shared__ float smem[];
    const int tid = threadIdx.x;
    const int lp = tid >> 3;   // local point 0..31
    const int q = tid & 7;     // owns rows q and q+8
    const int r1 = q + 8;
    const int p = blockIdx.x * PTS + lp;
    float* tile = smem + lp * PPB + TILE_OFF;
    float* Ss = smem + lp * PPB + S_OFF;   // stride 16
    float* Ps = smem + lp * PPB + P_OFF;   // stride 16

    // Exactly three register row-pairs live at any time: P, Y, T (96 floats).
    float P0[16], P1[16], Y0[16], Y1[16], T0[16], T1[16];

    ld_row16(P0, pi_Sigma + (size_t)p * 256 + q * 16);
    ld_row16(P1, pi_Sigma + (size_t)p * 256 + r1 * 16);
    {
        ld_row16(Y0, Sigma + (size_t)p * 256 + q * 16);
        ld_row16(Y1, Sigma + (size_t)p * 256 + r1 * 16);
        st_row16(Ss + q * 16, Y0);
        st_row16(Ss + r1 * 16, Y1);
    }

    // ---- mu update (rows q, q+8): mu + NSTEPS*dt * M_inv @ pi_mu ----
    {
        float pmv[16];
        ld_row16(pmv, pi_mu + (size_t)p * 16);
        const float* M0 = M_inv + (size_t)p * 256 + q * 16;
        const float* M1 = M_inv + (size_t)p * 256 + r1 * 16;
        float a0 = 0.0f, a1 = 0.0f;
#pragma unroll
        for (int j = 0; j < 16; j++) {
            a0 = fmaf(M0[j], pmv[j], a0);
            a1 = fmaf(M1[j], pmv[j], a1);
        }
        mu_o[(size_t)p * 16 + q]  = mu[(size_t)p * 16 + q]  + ((float)NSTEPS * DT) * a0;
        mu_o[(size_t)p * 16 + r1] = mu[(size_t)p * 16 + r1] + ((float)NSTEPS * DT) * a1;
    }

    // ---- phi update (thread q==0 of each point) ----
    if (q == 0) {
        float px = phi[p * 3 + 0], py = phi[p * 3 + 1], pz = phi[p * 3 + 2];
        const float vx = pi_phi[p * 3 + 0];
        const float vy = pi_phi[p * 3 + 1];
        const float vz = pi_phi[p * 3 + 2];
        const float TWO_PI = 6.283185307179586f;
        const float PI_F = 3.141592653589793f;
        const float R_MAX = 3.131592653589793f;
#pragma unroll 1
        for (int s = 0; s < NSTEPS; s++) {
            px += DT * vx; py += DT * vy; pz += DT * vz;
            float th = sqrtf(px * px + py * py + pz * pz);
            float ths = fmaxf(th, 1e-12f);
            float inv = 1.0f / ths;
            float ax = px * inv, ay = py * inv, az = pz * inv;
            float tw = fmodf(th, TWO_PI);
            bool flip = tw > PI_F;
            float tf = flip ? (TWO_PI - tw) : tw;
            if (flip) { ax = -ax; ay = -ay; az = -az; }
            tf = fminf(tf, R_MAX);
            px = ax * tf; py = ay * tf; pz = az * tf;
        }
        phi_o[p * 3 + 0] = px;
        phi_o[p * 3 + 1] = py;
        phi_o[p * 3 + 2] = pz;
    }
    __syncwarp();

#pragma unroll 1
    for (int step = 0; step < NSTEPS; step++) {
        // ===== kick1: P -= dt * (P*S)*P =====
        mm2z<16>(Y0, Y1, P0, P1, Ss);            // Y = P*S
#pragma unroll
        for (int j = 0; j < 16; j++) { Y0[j] *= -DT; Y1[j] *= -DT; }
        put2(tile, q, P0, P1);                   // tile <- P_old
        mm2a<TSTR>(P0, P1, Y0, Y1, tile);        // P += Y*P_old

        // ===== drift: S <- S * (Taylor4(dt*P*S))^2 =====
        mm2z<16>(Y0, Y1, P0, P1, Ss);            // Y = P*S
#pragma unroll
        for (int j = 0; j < 16; j++) { Y0[j] *= DT; Y1[j] *= DT; }
        if (step < NSTEPS - 1) {                 // stash P for kick2
            __syncwarp();
            st_row16(Ps + q * 16, P0);
            st_row16(Ps + r1 * 16, P1);
        }
        put2(tile, q, Y0, Y1);                   // tile <- Y
        mm2z<TSTR>(P0, P1, Y0, Y1, tile);        // P-slot = Y2 = Y*Y
        // T = (1/2)I + (1/6)Y + (1/24)Y2
#pragma unroll
        for (int j = 0; j < 16; j++) {
            T0[j] = fmaf(1.0f / 24.0f, P0[j], (1.0f / 6.0f) * Y0[j]);
            T1[j] = fmaf(1.0f / 24.0f, P1[j], (1.0f / 6.0f) * Y1[j]);
        }
        T0[q] += 0.5f; T1[r1] += 0.5f;
        // A0 = I + Y (overwrite Y)
        Y0[q] += 1.0f; Y1[r1] += 1.0f;
        put2(tile, q, T0, T1);                   // tile <- T
        mm2a<TSTR>(Y0, Y1, P0, P1, tile);        // Y = E4 = A0 + Y2*T
        put2(tile, q, Y0, Y1);                   // tile <- E4
        mm2z<TSTR>(T0, T1, Y0, Y1, tile);        // T = E = E4*E4
        put2(tile, q, T0, T1);                   // tile <- E
        ld_row16(Y0, Ss + q * 16);               // Y = S_old rows
        ld_row16(Y1, Ss + r1 * 16);
        mm2z<TSTR>(T0, T1, Y0, Y1, tile);        // T = S*E = S_new
        T0[q] += 1e-8f; T1[r1] += 1e-8f;
        __syncwarp();
        st_row16(Ss + q * 16, T0);
        st_row16(Ss + r1 * 16, T1);
        __syncwarp();

        // ===== kick2 (dead on last step: P not an output) =====
        if (step < NSTEPS - 1) {
            ld_row16(P0, Ps + q * 16);           // own rows, no sync needed
            ld_row16(P1, Ps + r1 * 16);
            mm2z<16>(Y0, Y1, P0, P1, Ss);        // Y = P*S_new
#pragma unroll
            for (int j = 0; j < 16; j++) { Y0[j] *= -DT; Y1[j] *= -DT; }
            put2(tile, q, P0, P1);
            mm2a<TSTR>(P0, P1, Y0, Y1, tile);    // P += Y*P_old
        }
    }

    // ---- final symmetrize (transpose via Ss) + store: T holds S_new ----
#pragma unroll
    for (int j = 0; j < 16; j++) {
        T0[j] = 0.5f * (T0[j] + Ss[j * 16 + q]);
        T1[j] = 0.5f * (T1[j] + Ss[j * 16 + r1]);
    }
    st_row16(Sig_o + (size_t)p * 256 + q * 16, T0);
    st_row16(Sig_o + (size_t)p * 256 + r1 * 16, T1);
}

extern "C" void kernel_launch(void* const* d_in, const int* in_sizes, int n_in,
                              void* d_out, int out_size) {
    const float* mu       = (const float*)d_in[0];
    const float* Sigma    = (const float*)d_in[1];
    const float* phi      = (const float*)d_in[2];
    const float* pi_mu    = (const float*)d_in[3];
    const float* pi_Sigma = (const float*)d_in[4];
    const float* pi_phi   = (const float*)d_in[5];
    const float* M_inv    = (const float*)d_in[6];

    const int npts = in_sizes[0] / 16;  // B*N = 32768
    float* out = (float*)d_out;
    float* mu_o  = out;
    float* Sig_o = out + (size_t)npts * 16;
    float* phi_o = out + (size_t)npts * 16 + (size_t)npts * 256;

    cudaFuncSetAttribute(ham_kernel, cudaFuncAttributeMaxDynamicSharedMemorySize,
                         SMEM_BYTES);

    dim3 grid(npts / PTS);
    dim3 block(NTHREADS);
    ham_kernel<<<grid, block, SMEM_BYTES>>>(mu, Sigma, phi, pi_mu, pi_Sigma,
                                            pi_phi, M_inv, mu_o, Sig_o, phi_o);
}